// round 4
// baseline (speedup 1.0000x reference)
#include <cuda_runtime.h>
#include <cuda_bf16.h>

// Problem constants
#define BB 8
#define LL 8192
#define DD 512
#define SF 4
#define RR 32               // rows per chunk
#define CH (LL / RR)        // 256 chunks per batch
#define GRID (BB * CH)      // 2048 blocks
#define OUT_L (LL / SF)     // 2048
#define D4 (DD / 4)         // 128 float4 lanes
#define OUTG (RR / SF)      // 8 output rows per chunk

// Decoupled-lookback state (16 MB scratch + flags + ticket)
__device__ float g_agg[BB][CH][DD];   // per-chunk aggregate (flag==1)
__device__ float g_inc[BB][CH][DD];   // per-chunk inclusive prefix (flag==2)
__device__ int g_flag[BB * CH];       // 0=empty, 1=aggregate ready, 2=inclusive ready
__device__ unsigned g_ticket;

__global__ void k_reset() {
    int i = blockIdx.x * blockDim.x + threadIdx.x;
    if (i < BB * CH) g_flag[i] = 0;
    if (i == 0) g_ticket = 0u;
}

__global__ __launch_bounds__(D4) void k_scan1p(const float* __restrict__ x,
                                               float* __restrict__ out) {
    __shared__ unsigned s_t;
    const int tid = threadIdx.x;
    if (tid == 0) s_t = atomicAdd(&g_ticket, 1u);
    __syncthreads();
    const unsigned t = s_t;          // ticket order == scheduling order -> progress
    const int b = (int)(t / CH);
    const int c = (int)(t % CH);
    const int d4 = tid;

    // ── Phase A: local chunk scan (single DRAM read of x) ──
    const float4* xp = reinterpret_cast<const float4*>(
        x + ((size_t)b * LL + (size_t)c * RR) * DD) + d4;
    float4 acc = make_float4(0.f, 0.f, 0.f, 0.f);
    float4 outp[OUTG];
#pragma unroll
    for (int g = 0; g < OUTG; ++g) {
#pragma unroll
        for (int s = 0; s < SF; ++s) {
            float4 v = xp[(size_t)(g * SF + s) * D4];
            acc.x += v.x; acc.y += v.y; acc.z += v.z; acc.w += v.w;
        }
        outp[g] = acc;               // partial prefix at this output point
    }

    int* flag_base = g_flag + b * CH;

    // ── Phase B: publish aggregate ASAP so successors can proceed ──
    if (c > 0 && c < CH - 1) {
        reinterpret_cast<float4*>(g_agg[b][c])[d4] = acc;
        __threadfence();
        __syncthreads();
        if (tid == 0) atomicExch(&flag_base[c], 1);
    }

    // ── Phase C: lookback for exclusive base (per-thread independent walk) ──
    float4 run = make_float4(0.f, 0.f, 0.f, 0.f);
    if (c > 0) {
        int p = c - 1;
        while (true) {
            volatile int* fp = (volatile int*)&flag_base[p];
            int f;
            while ((f = *fp) == 0) { }
            __threadfence();         // acquire: order flag read before data read
            if (f == 2) {
                float4 v = reinterpret_cast<const float4*>(g_inc[b][p])[d4];
                run.x += v.x; run.y += v.y; run.z += v.z; run.w += v.w;
                break;
            } else {
                float4 v = reinterpret_cast<const float4*>(g_agg[b][p])[d4];
                run.x += v.x; run.y += v.y; run.z += v.z; run.w += v.w;
                --p;                 // chunk 0 always publishes flag==2, so p>=0
            }
        }
    }

    // ── Phase D: publish inclusive prefix ──
    if (c < CH - 1) {
        float4 inc = make_float4(acc.x + run.x, acc.y + run.y,
                                 acc.z + run.z, acc.w + run.w);
        reinterpret_cast<float4*>(g_inc[b][c])[d4] = inc;
        __threadfence();
        __syncthreads();
        if (tid == 0) atomicExch(&flag_base[c], 2);
    }

    // ── Phase E: emit means ──
    float4* op = reinterpret_cast<float4*>(
        out + ((size_t)b * OUT_L + (size_t)c * OUTG) * DD) + d4;
#pragma unroll
    for (int g = 0; g < OUTG; ++g) {
        const float inv = 1.0f / (float)(c * RR + g * SF + SF);
        float4 o;
        o.x = (outp[g].x + run.x) * inv;
        o.y = (outp[g].y + run.y) * inv;
        o.z = (outp[g].z + run.z) * inv;
        o.w = (outp[g].w + run.w) * inv;
        op[(size_t)g * D4] = o;
    }
}

extern "C" void kernel_launch(void* const* d_in, const int* in_sizes, int n_in,
                              void* d_out, int out_size) {
    const float* x = (const float*)d_in[0];
    float* out = (float*)d_out;

    k_reset<<<(BB * CH + 255) / 256, 256>>>();
    k_scan1p<<<GRID, D4>>>(x, out);
}

// round 5
// speedup vs baseline: 1.4264x; 1.4264x over previous
#include <cuda_runtime.h>
#include <cuda_bf16.h>

// Problem constants
#define BB 8
#define LL 8192
#define DD 512
#define SF 4
#define CH 256              // chunks per batch
#define RR (LL / CH)        // 32 rows per chunk
#define OUT_L (LL / SF)     // 2048
#define D4 (DD / 4)         // 128 float4 lanes
#define OUTG (RR / SF)      // 8 output rows per chunk

// 4 MB scratch: per-chunk aggregates, then exclusive prefixes after k_scan
__device__ float g_part[BB][CH][DD];

// Phase 1: read x once; write unscaled partial prefixes straight into out,
// chunk aggregate into g_part. grid (CH, BB), 128 threads.
__global__ __launch_bounds__(D4) void k_pe(const float* __restrict__ x,
                                           float* __restrict__ out) {
    const int b = blockIdx.y;
    const int c = blockIdx.x;
    const int d4 = threadIdx.x;
    const float4* xp = reinterpret_cast<const float4*>(
        x + ((size_t)b * LL + (size_t)c * RR) * DD) + d4;
    float4* op = reinterpret_cast<float4*>(
        out + ((size_t)b * OUT_L + (size_t)c * OUTG) * DD) + d4;

    float4 acc = make_float4(0.f, 0.f, 0.f, 0.f);
#pragma unroll
    for (int g = 0; g < OUTG; ++g) {
        // 4 independent loads; pairwise tree add shortens the dependent chain
        float4 v0 = xp[(size_t)(g * SF + 0) * D4];
        float4 v1 = xp[(size_t)(g * SF + 1) * D4];
        float4 v2 = xp[(size_t)(g * SF + 2) * D4];
        float4 v3 = xp[(size_t)(g * SF + 3) * D4];
        float4 s;
        s.x = (v0.x + v1.x) + (v2.x + v3.x);
        s.y = (v0.y + v1.y) + (v2.y + v3.y);
        s.z = (v0.z + v1.z) + (v2.z + v3.z);
        s.w = (v0.w + v1.w) + (v2.w + v3.w);
        acc.x += s.x; acc.y += s.y; acc.z += s.z; acc.w += s.w;
        op[(size_t)g * D4] = acc;   // unscaled partial prefix, fixed up in k_fix
    }
    reinterpret_cast<float4*>(g_part[b][c])[d4] = acc;
}

// Phase 2: exclusive prefix over chunk aggregates, per (b, d). grid BB, 512 thr.
__global__ void k_scan() {
    const int b = blockIdx.x;
    const int d = threadIdx.x;
    float run = 0.f;
#pragma unroll 8
    for (int c = 0; c < CH; ++c) {
        float t = g_part[b][c][d];
        g_part[b][c][d] = run;
        run += t;
    }
}

// Phase 3: in-place fixup of out: add exclusive base, scale to mean.
// grid (CH, BB), 128 threads. No x re-read.
__global__ __launch_bounds__(D4) void k_fix(float* __restrict__ out) {
    const int b = blockIdx.y;
    const int c = blockIdx.x;
    const int d4 = threadIdx.x;
    const float4 base = reinterpret_cast<const float4*>(g_part[b][c])[d4];
    float4* op = reinterpret_cast<float4*>(
        out + ((size_t)b * OUT_L + (size_t)c * OUTG) * DD) + d4;

#pragma unroll
    for (int g = 0; g < OUTG; ++g) {
        const float inv = 1.0f / (float)(c * RR + g * SF + SF);
        float4 v = op[(size_t)g * D4];
        v.x = (v.x + base.x) * inv;
        v.y = (v.y + base.y) * inv;
        v.z = (v.z + base.z) * inv;
        v.w = (v.w + base.w) * inv;
        op[(size_t)g * D4] = v;
    }
}

extern "C" void kernel_launch(void* const* d_in, const int* in_sizes, int n_in,
                              void* d_out, int out_size) {
    const float* x = (const float*)d_in[0];
    float* out = (float*)d_out;

    dim3 grid(CH, BB);
    k_pe<<<grid, D4>>>(x, out);
    k_scan<<<BB, DD>>>();
    k_fix<<<grid, D4>>>(out);
}

// round 6
// speedup vs baseline: 1.6112x; 1.1296x over previous
#include <cuda_runtime.h>
#include <cuda_bf16.h>

// Problem constants
#define BB 8
#define LL 8192
#define DD 512
#define SF 4
#define CH 256              // chunks per batch
#define RR (LL / CH)        // 32 rows per chunk
#define OUT_L (LL / SF)     // 2048
#define D4 (DD / 4)         // 128 float4 lanes
#define OUTG (RR / SF)      // 8 output rows per chunk

// 4 MB scratch: per-chunk aggregates, then exclusive prefixes after k_scan
__device__ float g_part[BB][CH][DD];

// Phase 1: read x once (streaming, evict-first -> keep out/g_part L2-resident);
// write unscaled partial prefixes into out, chunk aggregate into g_part.
// grid (CH, BB), 128 threads. 8 independent LDG.128 in flight per batch.
__global__ __launch_bounds__(D4) void k_pe(const float* __restrict__ x,
                                           float* __restrict__ out) {
    const int b = blockIdx.y;
    const int c = blockIdx.x;
    const int d4 = threadIdx.x;
    const float4* xp = reinterpret_cast<const float4*>(
        x + ((size_t)b * LL + (size_t)c * RR) * DD) + d4;
    float4* op = reinterpret_cast<float4*>(
        out + ((size_t)b * OUT_L + (size_t)c * OUTG) * DD) + d4;

    float4 acc = make_float4(0.f, 0.f, 0.f, 0.f);
#pragma unroll
    for (int g2 = 0; g2 < RR / 8; ++g2) {      // 4 batches of 8 rows
        float4 v[8];
#pragma unroll
        for (int r = 0; r < 8; ++r)             // 8 loads in flight (evict-first)
            v[r] = __ldcs(xp + (size_t)(g2 * 8 + r) * D4);

        // first output point (rows 0..3 of batch)
        acc.x += (v[0].x + v[1].x) + (v[2].x + v[3].x);
        acc.y += (v[0].y + v[1].y) + (v[2].y + v[3].y);
        acc.z += (v[0].z + v[1].z) + (v[2].z + v[3].z);
        acc.w += (v[0].w + v[1].w) + (v[2].w + v[3].w);
        op[(size_t)(g2 * 2 + 0) * D4] = acc;

        // second output point (rows 4..7 of batch)
        acc.x += (v[4].x + v[5].x) + (v[6].x + v[7].x);
        acc.y += (v[4].y + v[5].y) + (v[6].y + v[7].y);
        acc.z += (v[4].z + v[5].z) + (v[6].z + v[7].z);
        acc.w += (v[4].w + v[5].w) + (v[6].w + v[7].w);
        op[(size_t)(g2 * 2 + 1) * D4] = acc;
    }
    reinterpret_cast<float4*>(g_part[b][c])[d4] = acc;
}

// Phase 2: exclusive prefix over chunk aggregates, per (b, d).
// grid (4, BB) x 128 threads -> 32 blocks (was 8: LSU-starved on 8 SMs).
__global__ __launch_bounds__(128) void k_scan() {
    const int b = blockIdx.y;
    const int d = blockIdx.x * 128 + threadIdx.x;
    float run = 0.f;
#pragma unroll 8
    for (int c = 0; c < CH; ++c) {
        float t = g_part[b][c][d];
        g_part[b][c][d] = run;
        run += t;
    }
}

// Phase 3: in-place fixup of out (L2-resident after k_pe thanks to __ldcs on x):
// add exclusive base, scale to mean. grid (CH, BB), 128 threads.
__global__ __launch_bounds__(D4) void k_fix(float* __restrict__ out) {
    const int b = blockIdx.y;
    const int c = blockIdx.x;
    const int d4 = threadIdx.x;
    const float4 base = reinterpret_cast<const float4*>(g_part[b][c])[d4];
    float4* op = reinterpret_cast<float4*>(
        out + ((size_t)b * OUT_L + (size_t)c * OUTG) * DD) + d4;

#pragma unroll
    for (int g = 0; g < OUTG; ++g) {
        const float inv = 1.0f / (float)(c * RR + g * SF + SF);
        float4 v = op[(size_t)g * D4];
        v.x = (v.x + base.x) * inv;
        v.y = (v.y + base.y) * inv;
        v.z = (v.z + base.z) * inv;
        v.w = (v.w + base.w) * inv;
        op[(size_t)g * D4] = v;
    }
}

extern "C" void kernel_launch(void* const* d_in, const int* in_sizes, int n_in,
                              void* d_out, int out_size) {
    const float* x = (const float*)d_in[0];
    float* out = (float*)d_out;

    dim3 grid(CH, BB);
    k_pe<<<grid, D4>>>(x, out);
    k_scan<<<dim3(4, BB), 128>>>();
    k_fix<<<grid, D4>>>(out);
}

// round 7
// speedup vs baseline: 1.6693x; 1.0361x over previous
#include <cuda_runtime.h>
#include <cuda_bf16.h>

// Problem constants
#define BB 8
#define LL 8192
#define DD 512
#define SF 4
#define RR 32               // rows per chunk
#define CH (LL / RR)        // 256 chunks per batch
#define GRID (BB * CH)      // 2048 blocks
#define OUT_L (LL / SF)     // 2048
#define D4 (DD / 4)         // 128 float4 lanes
#define OUTG (RR / SF)      // 8 output rows per chunk

// Lookback state (8 MB value scratch, L2-resident)
__device__ float g_agg[BB][CH][DD];   // per-chunk aggregate   (flag>=1)
__device__ float g_inc[BB][CH][DD];   // per-chunk inclusive   (flag==2)
__device__ int g_flag[BB * CH];       // 0=empty 1=agg ready 2=inclusive ready
__device__ unsigned g_ticket;

__device__ __forceinline__ int ld_acq(const int* p) {
    int v;
    asm volatile("ld.acquire.gpu.s32 %0, [%1];" : "=r"(v) : "l"(p) : "memory");
    return v;
}

__global__ void k_reset() {
    int i = blockIdx.x * blockDim.x + threadIdx.x;
    if (i < BB * CH) g_flag[i] = 0;
    if (i == 0) g_ticket = 0u;
}

__global__ __launch_bounds__(D4) void k_main(const float* __restrict__ x,
                                             float* __restrict__ out) {
    __shared__ unsigned s_t;
    __shared__ int s_limit;   // predecessors consumed this window
    __shared__ int s_found;   // 1 if window contains an inclusive
    const int tid = threadIdx.x;
    if (tid == 0) s_t = atomicAdd(&g_ticket, 1u);
    __syncthreads();
    const unsigned t = s_t;              // acquisition order == scheduling order
    const int b = (int)(t / CH);
    const int c = (int)(t % CH);
    const int d4 = tid;

    // ── Phase A: local chunk scan; partials stay in registers ──
    const float4* xp = reinterpret_cast<const float4*>(
        x + ((size_t)b * LL + (size_t)c * RR) * DD) + d4;
    float4 acc = make_float4(0.f, 0.f, 0.f, 0.f);
    float4 outp[OUTG];
#pragma unroll
    for (int g = 0; g < OUTG; ++g) {
        float4 v0 = __ldcs(xp + (size_t)(g * SF + 0) * D4);
        float4 v1 = __ldcs(xp + (size_t)(g * SF + 1) * D4);
        float4 v2 = __ldcs(xp + (size_t)(g * SF + 2) * D4);
        float4 v3 = __ldcs(xp + (size_t)(g * SF + 3) * D4);
        acc.x += (v0.x + v1.x) + (v2.x + v3.x);
        acc.y += (v0.y + v1.y) + (v2.y + v3.y);
        acc.z += (v0.z + v1.z) + (v2.z + v3.z);
        acc.w += (v0.w + v1.w) + (v2.w + v3.w);
        outp[g] = acc;
    }

    int* flag_base = g_flag + b * CH;

    // ── Phase B: publish aggregate ASAP (release) ──
    if (c > 0 && c < CH - 1) {
        reinterpret_cast<float4*>(g_agg[b][c])[d4] = acc;
        __threadfence();
        __syncthreads();
        if (tid == 0) atomicExch(&flag_base[c], 1);
    }

    // ── Phase C: warp-parallel windowed lookback ──
    float4 run = make_float4(0.f, 0.f, 0.f, 0.f);
    if (c > 0) {
        int p = c - 1;                   // highest unconsumed predecessor
        for (;;) {
            const int W = (p + 1 < 32) ? (p + 1) : 32;
            // warp 0: poll this window's flags (one flag per lane)
            if (tid < 32) {
                int f = 0;
                if (tid < W) {
                    const int* fp = &flag_base[p - tid];
                    f = ld_acq(fp);
                    while (f == 0) { __nanosleep(64); f = ld_acq(fp); }
                }
                unsigned done_mask = __ballot_sync(0xFFFFFFFFu, f == 2);
                if (tid == 0) {
                    if (done_mask) {
                        s_limit = __ffs(done_mask) - 1;  // nearest inclusive
                        s_found = 1;
                    } else {
                        s_limit = W - 1;                 // consume whole window
                        s_found = 0;
                    }
                }
            }
            __syncthreads();
            const int limit = s_limit;
            const int found = s_found;
            __syncthreads();
            // all threads: sum up to 32 independent value vectors (L2, MLP-rich)
            for (int j = 0; j <= limit; ++j) {
                const int q = p - j;
                const float* src = (found && j == limit) ? g_inc[b][q] : g_agg[b][q];
                float4 v = reinterpret_cast<const float4*>(src)[d4];
                run.x += v.x; run.y += v.y; run.z += v.z; run.w += v.w;
            }
            if (found) break;
            p -= W;                      // chunk 0 publishes flag==2, so p>=0
        }
    }

    // ── Phase D: publish inclusive (release) ──
    if (c < CH - 1) {
        float4 inc = make_float4(acc.x + run.x, acc.y + run.y,
                                 acc.z + run.z, acc.w + run.w);
        reinterpret_cast<float4*>(g_inc[b][c])[d4] = inc;
        __threadfence();
        __syncthreads();
        if (tid == 0) atomicExch(&flag_base[c], 2);
    }

    // ── Phase E: emit final scaled means (single write of out) ──
    float4* op = reinterpret_cast<float4*>(
        out + ((size_t)b * OUT_L + (size_t)c * OUTG) * DD) + d4;
#pragma unroll
    for (int g = 0; g < OUTG; ++g) {
        const float inv = 1.0f / (float)(c * RR + g * SF + SF);
        float4 o;
        o.x = (outp[g].x + run.x) * inv;
        o.y = (outp[g].y + run.y) * inv;
        o.z = (outp[g].z + run.z) * inv;
        o.w = (outp[g].w + run.w) * inv;
        op[(size_t)g * D4] = o;
    }
}

extern "C" void kernel_launch(void* const* d_in, const int* in_sizes, int n_in,
                              void* d_out, int out_size) {
    const float* x = (const float*)d_in[0];
    float* out = (float*)d_out;

    k_reset<<<(BB * CH + 255) / 256, 256>>>();
    k_main<<<GRID, D4>>>(x, out);
}